// round 5
// baseline (speedup 1.0000x reference)
#include <cuda_runtime.h>
#include <cuda_bf16.h>
#include <cstddef>
#include <cstring>

// Problem constants (fixed by the reference)
#define NPTS 16384
#define CH   192
#define NH   16
#define NK   43
#define DEPTH 2
#define BN_EPS 1e-5f
#define PAIRS 8          // point-pairs per conv block (16 points)

typedef unsigned long long ull;

// ---------------- scratch (device globals; no allocation allowed) ----------
__device__ float g_tmp1[NPTS * CH];
__device__ float g_tmp2[NPTS * CH];
__device__ float g_tmp3[NPTS * CH];
__device__ float g_featbuf[NPTS * CH];
__device__ float g_stats[6 * 2 * CH];   // 6 stages x (sum[CH], sumsq[CH])
__device__ float g_st[6 * 2 * CH];      // 6 stages x (scale[CH], shift[CH])

// ---------------- f32x2 packed helpers -------------------------------------
__device__ __forceinline__ ull pack2(float x, float y) {
    ull r;
    asm("mov.b64 %0, {%1, %2};" : "=l"(r) : "f"(x), "f"(y));
    return r;
}
__device__ __forceinline__ void ffma2(ull& d, ull a, ull b) {
    asm("fma.rn.f32x2 %0, %1, %2, %0;" : "+l"(d) : "l"(a), "l"(b));
}
__device__ __forceinline__ float2 unpack2(ull v) {
    float2 r;
    asm("mov.b64 {%0, %1}, %2;" : "=f"(r.x), "=f"(r.y) : "l"(v));
    return r;
}

// ---------------------------------------------------------------------------
__global__ void zero_stats_kernel(float* stats) {
    for (int i = threadIdx.x; i < 6 * 2 * CH; i += blockDim.x) stats[i] = 0.f;
}

// finalize BN: scale = g * rsqrt(var+eps), shift = b - mean*scale
__global__ void fin_kernel(const float* __restrict__ stats,
                           const float* __restrict__ g,
                           const float* __restrict__ b,
                           float* __restrict__ st) {
    int c = threadIdx.x;   // 192 threads
    float m = stats[c] * (1.0f / NPTS);
    float v = stats[CH + c] * (1.0f / NPTS) - m * m;
    float s = g[c] * rsqrtf(v + BN_EPS);
    st[c]      = s;
    st[CH + c] = b[c] - m * s;
}

// ---------------------------------------------------------------------------
// GEMM: out[N,192] = act(A)[N,192] @ W[192,192], f32x2 packed inner loop.
// Optional fused BN+ReLU on A load (fuse != 0). Accumulates per-channel
// sum / sumsq for the next BN. Block: 256 threads, 64 rows x 192 cols.
// Thread (tx,ty): rows ty*8..ty*8+7, channel pairs (2tx+64j, 2tx+64j+1), j<3.
__global__ __launch_bounds__(256) void gemm192_kernel(
    const float* __restrict__ A, const float* __restrict__ W,
    float* __restrict__ out, const float* __restrict__ st_in, int fuse,
    float* __restrict__ gsum, float* __restrict__ gsq)
{
    __shared__ __align__(16) ull   sAd[64][33];   // duplicated (a,a) pairs, padded
    __shared__ __align__(16) float sB[32][192];

    const int tid = threadIdx.x;
    const int tx  = tid & 31;        // 0..31
    const int ty  = tid >> 5;        // 0..7
    const int row0 = blockIdx.x * 64;

    ull acc[8][3];
#pragma unroll
    for (int r = 0; r < 8; r++)
#pragma unroll
        for (int j = 0; j < 3; j++) acc[r][j] = 0ull;

    for (int k0 = 0; k0 < 192; k0 += 32) {
        // --- load A tile (64x32) as float4, optional BN+ReLU, store dup ---
#pragma unroll
        for (int it = tid; it < 512; it += 256) {
            int r  = it >> 3;
            int kq = it & 7;
            float4 v = *(const float4*)(A + (size_t)(row0 + r) * CH + k0 + kq * 4);
            if (fuse) {
                float4 s = *(const float4*)(st_in + k0 + kq * 4);
                float4 t = *(const float4*)(st_in + CH + k0 + kq * 4);
                v.x = fmaxf(fmaf(v.x, s.x, t.x), 0.f);
                v.y = fmaxf(fmaf(v.y, s.y, t.y), 0.f);
                v.z = fmaxf(fmaf(v.z, s.z, t.z), 0.f);
                v.w = fmaxf(fmaf(v.w, s.w, t.w), 0.f);
            }
            sAd[r][kq * 4 + 0] = pack2(v.x, v.x);
            sAd[r][kq * 4 + 1] = pack2(v.y, v.y);
            sAd[r][kq * 4 + 2] = pack2(v.z, v.z);
            sAd[r][kq * 4 + 3] = pack2(v.w, v.w);
        }
        // --- load B tile (32x192) ---
#pragma unroll
        for (int it = tid; it < 1536; it += 256) {
            int kk = it / 48;
            int cq = it - kk * 48;
            *(float4*)&sB[kk][cq * 4] =
                *(const float4*)(W + (size_t)(k0 + kk) * CH + cq * 4);
        }
        __syncthreads();

#pragma unroll 8
        for (int kk = 0; kk < 32; kk++) {
            ull bp[3];
#pragma unroll
            for (int j = 0; j < 3; j++)
                bp[j] = *(const ull*)&sB[kk][2 * tx + 64 * j];
#pragma unroll
            for (int r = 0; r < 8; r++) {
                ull ap = sAd[ty * 8 + r][kk];
                ffma2(acc[r][0], ap, bp[0]);
                ffma2(acc[r][1], ap, bp[1]);
                ffma2(acc[r][2], ap, bp[2]);
            }
        }
        __syncthreads();
    }

    // --- write out + per-channel stats ---
    float cs[3][2], c2[3][2];
#pragma unroll
    for (int j = 0; j < 3; j++) {
        cs[j][0] = cs[j][1] = 0.f;
        c2[j][0] = c2[j][1] = 0.f;
    }
#pragma unroll
    for (int r = 0; r < 8; r++) {
        float* orow = out + (size_t)(row0 + ty * 8 + r) * CH;
#pragma unroll
        for (int j = 0; j < 3; j++) {
            float2 v = unpack2(acc[r][j]);
            *(float2*)(orow + 2 * tx + 64 * j) = v;
            cs[j][0] += v.x;           cs[j][1] += v.y;
            c2[j][0] = fmaf(v.x, v.x, c2[j][0]);
            c2[j][1] = fmaf(v.y, v.y, c2[j][1]);
        }
    }
#pragma unroll
    for (int j = 0; j < 3; j++) {
        atomicAdd(&gsum[2 * tx + 64 * j],     cs[j][0]);
        atomicAdd(&gsum[2 * tx + 64 * j + 1], cs[j][1]);
        atomicAdd(&gsq [2 * tx + 64 * j],     c2[j][0]);
        atomicAdd(&gsq [2 * tx + 64 * j + 1], c2[j][1]);
    }
}

// ---------------------------------------------------------------------------
// Depthwise kernel-point conv, f32x2 packed over POINT PAIRS.
// One block = 192 threads (one per channel), PAIRS point-pairs per block.
// Influence stored interleaved [k][2h+p] so each LDS.128 yields two packed
// (p0,p1) operands. BN1+ReLU fused at gather; BN2 stats accumulated.
__global__ __launch_bounds__(192) void conv_kernel(
    const float* __restrict__ coord, const int* __restrict__ ref_idx,
    const float* __restrict__ kp, const float* __restrict__ tmp1,
    const float* __restrict__ st1, const float* __restrict__ Wk,
    float* __restrict__ out,
    float* __restrict__ gsum, float* __restrict__ gsq)
{
    __shared__ __align__(16) float s_wk[NK * CH];          // 33 KB
    __shared__ __align__(16) float s_infl2[NK][2 * NH];    // [k][2h+p]  5.4 KB
    __shared__ int   s_ref[2][NH];
    __shared__ float s_nb[2][NH][3];
    __shared__ float s_kp[NK * 3];

    const int tid = threadIdx.x;   // channel index
    for (int i = tid; i < NK * CH; i += 192) s_wk[i] = Wk[i];
    for (int i = tid; i < NK * 3;  i += 192) s_kp[i] = kp[i];

    const float s1c = st1[tid];
    const float t1c = st1[CH + tid];
    float lsum = 0.f, lsq = 0.f;

    for (int pp = 0; pp < PAIRS; pp++) {
        const int n0 = (blockIdx.x * PAIRS + pp) * 2;
        __syncthreads();   // prev iteration done reading s_ref / s_infl2
        if (tid < 32) {
            int p = tid >> 4;          // 0/1 point of pair
            int h = tid & 15;
            int n = n0 + p;
            int r = ref_idx[n * NH + h];
            s_ref[p][h] = r;
            s_nb[p][h][0] = coord[r * 3 + 0] - coord[n * 3 + 0];
            s_nb[p][h][1] = coord[r * 3 + 1] - coord[n * 3 + 1];
            s_nb[p][h][2] = coord[r * 3 + 2] - coord[n * 3 + 2];
        }
        __syncthreads();
        for (int i = tid; i < NH * NK; i += 192) {
            int h = i / NK;
            int k = i - h * NK;
            float kx = s_kp[k * 3 + 0], ky = s_kp[k * 3 + 1], kz = s_kp[k * 3 + 2];
#pragma unroll
            for (int p = 0; p < 2; p++) {
                float dx = s_nb[p][h][0] - kx;
                float dy = s_nb[p][h][1] - ky;
                float dz = s_nb[p][h][2] - kz;
                float d  = sqrtf(fmaf(dx, dx, fmaf(dy, dy, dz * dz)));
                s_infl2[k][2 * h + p] = fmaxf(1.0f - d, 0.0f);   // SIGMA == 1
            }
        }
        __syncthreads();

        // acc[h] (pair over points) = sum_k infl2[k][h] * (w,w)
        ull acc[NH];
#pragma unroll
        for (int h = 0; h < NH; h++) acc[h] = 0ull;
#pragma unroll
        for (int k = 0; k < NK; k++) {
            float w = s_wk[k * CH + tid];
            ull w2 = pack2(w, w);
            const ulonglong2* ip = (const ulonglong2*)&s_infl2[k][0];
#pragma unroll
            for (int h2 = 0; h2 < 8; h2++) {
                ulonglong2 u = ip[h2];        // LDS.128 broadcast: 2 packed pairs
                ffma2(acc[2 * h2 + 0], u.x, w2);
                ffma2(acc[2 * h2 + 1], u.y, w2);
            }
        }

        // gather fc1 rows (BN1+ReLU fused) and aggregate, both points
        float o0 = 0.f, o1 = 0.f;
#pragma unroll
        for (int h = 0; h < NH; h++) {
            float2 a = unpack2(acc[h]);
            float x0 = __ldg(tmp1 + s_ref[0][h] * CH + tid);
            x0 = fmaxf(fmaf(x0, s1c, t1c), 0.f);
            o0 = fmaf(a.x, x0, o0);
            float x1 = __ldg(tmp1 + s_ref[1][h] * CH + tid);
            x1 = fmaxf(fmaf(x1, s1c, t1c), 0.f);
            o1 = fmaf(a.y, x1, o1);
        }
        out[n0 * CH + tid]      = o0;
        out[(n0 + 1) * CH + tid] = o1;
        lsum += o0 + o1;
        lsq  = fmaf(o0, o0, fmaf(o1, o1, lsq));
    }
    atomicAdd(&gsum[tid], lsum);
    atomicAdd(&gsq [tid], lsq);
}

// ---------------------------------------------------------------------------
// feat_out = relu(identity + BN3(tmp3))   (vectorized float4)
__global__ __launch_bounds__(256) void apply3_kernel(
    const float4* __restrict__ idf, const float4* __restrict__ t3,
    const float* __restrict__ st, float4* __restrict__ outf)
{
    int i  = blockIdx.x * blockDim.x + threadIdx.x;   // < NPTS*CH/4
    int cq = i % (CH / 4);
    float4 s = *(const float4*)(st + cq * 4);
    float4 t = *(const float4*)(st + CH + cq * 4);
    float4 x = t3[i];
    float4 d = idf[i];
    float4 r;
    r.x = fmaxf(d.x + fmaf(x.x, s.x, t.x), 0.f);
    r.y = fmaxf(d.y + fmaf(x.y, s.y, t.y), 0.f);
    r.z = fmaxf(d.z + fmaf(x.z, s.z, t.z), 0.f);
    r.w = fmaxf(d.w + fmaf(x.w, s.w, t.w), 0.f);
    outf[i] = r;
}

// ---------------------------------------------------------------------------
extern "C" void kernel_launch(void* const* d_in, const int* in_sizes, int n_in,
                              void* d_out, int out_size)
{
    const float* coord   = (const float*)d_in[0];
    const float* feat    = (const float*)d_in[1];
    const int*   ref_idx = (const int*)  d_in[2];
    const float* kp      = (const float*)d_in[3];
    const float* W1      = (const float*)d_in[4];
    const float* Wk      = (const float*)d_in[5];
    const float* W3      = (const float*)d_in[6];
    const float* g1      = (const float*)d_in[7];
    const float* b1      = (const float*)d_in[8];
    const float* g2      = (const float*)d_in[9];
    const float* b2      = (const float*)d_in[10];
    const float* g3      = (const float*)d_in[11];
    const float* b3      = (const float*)d_in[12];
    float* out = (float*)d_out;

    float *tmp1, *tmp2, *tmp3, *featbuf, *stats, *st;
    cudaGetSymbolAddress((void**)&tmp1,    g_tmp1);
    cudaGetSymbolAddress((void**)&tmp2,    g_tmp2);
    cudaGetSymbolAddress((void**)&tmp3,    g_tmp3);
    cudaGetSymbolAddress((void**)&featbuf, g_featbuf);
    cudaGetSymbolAddress((void**)&stats,   g_stats);
    cudaGetSymbolAddress((void**)&st,      g_st);

    zero_stats_kernel<<<1, 256>>>(stats);

    const int NVEC = NPTS * CH / 4;             // 786432
    for (int i = 0; i < DEPTH; i++) {
        const float* fin_ = (i == 0) ? feat : featbuf;
        float* fout = (i == DEPTH - 1) ? out : featbuf;
        const int s0 = 3 * i + 0, s1 = 3 * i + 1, s2 = 3 * i + 2;

        // fc1 (+BN1 stats)
        gemm192_kernel<<<NPTS / 64, 256>>>(
            fin_, W1 + (size_t)i * CH * CH, tmp1, nullptr, 0,
            stats + s0 * 2 * CH, stats + s0 * 2 * CH + CH);
        fin_kernel<<<1, CH>>>(stats + s0 * 2 * CH, g1 + i * CH, b1 + i * CH,
                              st + s0 * 2 * CH);

        // KP depthwise conv (BN1+ReLU fused at gather; BN2 stats out)
        conv_kernel<<<NPTS / (2 * PAIRS), CH>>>(
            coord, ref_idx, kp, tmp1, st + s0 * 2 * CH,
            Wk + (size_t)i * NK * CH, tmp2,
            stats + s1 * 2 * CH, stats + s1 * 2 * CH + CH);
        fin_kernel<<<1, CH>>>(stats + s1 * 2 * CH, g2 + i * CH, b2 + i * CH,
                              st + s1 * 2 * CH);

        // fc3 (BN2+ReLU fused on A load; BN3 stats out)
        gemm192_kernel<<<NPTS / 64, 256>>>(
            tmp2, W3 + (size_t)i * CH * CH, tmp3, st + s1 * 2 * CH, 1,
            stats + s2 * 2 * CH, stats + s2 * 2 * CH + CH);
        fin_kernel<<<1, CH>>>(stats + s2 * 2 * CH, g3 + i * CH, b3 + i * CH,
                              st + s2 * 2 * CH);

        // skip + BN3 + ReLU
        apply3_kernel<<<NVEC / 256, 256>>>(
            (const float4*)fin_, (const float4*)tmp3, st + s2 * 2 * CH,
            (float4*)fout);
    }
}

// round 6
// speedup vs baseline: 1.2034x; 1.2034x over previous
#include <cuda_runtime.h>
#include <cuda_bf16.h>
#include <cstddef>

// Problem constants (fixed by the reference)
#define NPTS 16384
#define CH   192
#define NH   16
#define NK   43
#define DEPTH 2
#define BN_EPS 1e-5f
#define GROUPS 8         // point-groups (4 points each) per conv block

typedef unsigned long long ull;

// ---------------- scratch (device globals; no allocation allowed) ----------
__device__ float g_tmp1[NPTS * CH];
__device__ float g_tmp2[NPTS * CH];
__device__ float g_tmp3[NPTS * CH];
__device__ float g_featbuf[NPTS * CH];
__device__ float g_stats[6 * 2 * CH];   // 6 stages x (sum[CH], sumsq[CH])
__device__ float g_st[6 * 2 * CH];      // 6 stages x (scale[CH], shift[CH])

// ---------------- f32x2 packed helpers -------------------------------------
__device__ __forceinline__ ull pack2(float x, float y) {
    ull r;
    asm("mov.b64 %0, {%1, %2};" : "=l"(r) : "f"(x), "f"(y));
    return r;
}
__device__ __forceinline__ void ffma2(ull& d, ull a, ull b) {
    asm("fma.rn.f32x2 %0, %1, %2, %0;" : "+l"(d) : "l"(a), "l"(b));
}
__device__ __forceinline__ float2 unpack2(ull v) {
    float2 r;
    asm("mov.b64 {%0, %1}, %2;" : "=f"(r.x), "=f"(r.y) : "l"(v));
    return r;
}
__device__ __forceinline__ float fast_sqrt(float x) {
    float r;
    asm("sqrt.approx.f32 %0, %1;" : "=f"(r) : "f"(x));
    return r;
}

// ---------------------------------------------------------------------------
__global__ void zero_stats_kernel(float* stats) {
    for (int i = threadIdx.x; i < 6 * 2 * CH; i += blockDim.x) stats[i] = 0.f;
}

// finalize BN: scale = g * rsqrt(var+eps), shift = b - mean*scale
__global__ void fin_kernel(const float* __restrict__ stats,
                           const float* __restrict__ g,
                           const float* __restrict__ b,
                           float* __restrict__ st) {
    int c = threadIdx.x;   // 192 threads
    float m = stats[c] * (1.0f / NPTS);
    float v = stats[CH + c] * (1.0f / NPTS) - m * m;
    float s = g[c] * rsqrtf(v + BN_EPS);
    st[c]      = s;
    st[CH + c] = b[c] - m * s;
}

// ---------------------------------------------------------------------------
// GEMM: out[N,192] = act(A)[N,192] @ W[192,192]  (R3 scalar version — known
// good at ~15 T FMA/s). Optional fused BN+ReLU on A load. Accumulates
// per-channel sum / sumsq for the next BN. Block: 256 threads, 64x192 tile.
__global__ __launch_bounds__(256) void gemm192_kernel(
    const float* __restrict__ A, const float* __restrict__ W,
    float* __restrict__ out, const float* __restrict__ st_in, int fuse,
    float* __restrict__ gsum, float* __restrict__ gsq)
{
    __shared__ __align__(16) float sA[64][32];
    __shared__ __align__(16) float sB[32][192];

    const int tid = threadIdx.x;
    const int tx  = tid & 31;        // 0..31
    const int ty  = tid >> 5;        // 0..7
    const int row0 = blockIdx.x * 64;

    float acc[8][6];
#pragma unroll
    for (int r = 0; r < 8; r++)
#pragma unroll
        for (int q = 0; q < 6; q++) acc[r][q] = 0.f;

    for (int k0 = 0; k0 < 192; k0 += 32) {
        // --- load A tile (64x32) as float4, optional BN+ReLU transform ---
#pragma unroll
        for (int it = tid; it < 512; it += 256) {
            int r  = it >> 3;
            int kq = it & 7;
            float4 v = *(const float4*)(A + (size_t)(row0 + r) * CH + k0 + kq * 4);
            if (fuse) {
                float4 s = *(const float4*)(st_in + k0 + kq * 4);
                float4 t = *(const float4*)(st_in + CH + k0 + kq * 4);
                v.x = fmaxf(fmaf(v.x, s.x, t.x), 0.f);
                v.y = fmaxf(fmaf(v.y, s.y, t.y), 0.f);
                v.z = fmaxf(fmaf(v.z, s.z, t.z), 0.f);
                v.w = fmaxf(fmaf(v.w, s.w, t.w), 0.f);
            }
            *(float4*)&sA[r][kq * 4] = v;
        }
        // --- load B tile (32x192) ---
#pragma unroll
        for (int it = tid; it < 1536; it += 256) {
            int kk = it / 48;
            int cq = it - kk * 48;
            *(float4*)&sB[kk][cq * 4] =
                *(const float4*)(W + (size_t)(k0 + kk) * CH + cq * 4);
        }
        __syncthreads();

#pragma unroll
        for (int kk4 = 0; kk4 < 8; kk4++) {
            float4 av[8];
#pragma unroll
            for (int r = 0; r < 8; r++)
                av[r] = *(const float4*)&sA[ty * 8 + r][kk4 * 4];
#pragma unroll
            for (int j = 0; j < 4; j++) {
                float bv[6];
#pragma unroll
                for (int q = 0; q < 6; q++)
                    bv[q] = sB[kk4 * 4 + j][tx + 32 * q];
#pragma unroll
                for (int r = 0; r < 8; r++) {
                    float a = (j == 0) ? av[r].x : (j == 1) ? av[r].y
                            : (j == 2) ? av[r].z : av[r].w;
#pragma unroll
                    for (int q = 0; q < 6; q++)
                        acc[r][q] = fmaf(a, bv[q], acc[r][q]);
                }
            }
        }
        __syncthreads();
    }

    // --- write out + per-channel stats ---
    float cs[6], c2[6];
#pragma unroll
    for (int q = 0; q < 6; q++) { cs[q] = 0.f; c2[q] = 0.f; }
#pragma unroll
    for (int r = 0; r < 8; r++) {
        float* orow = out + (size_t)(row0 + ty * 8 + r) * CH;
#pragma unroll
        for (int q = 0; q < 6; q++) {
            float v = acc[r][q];
            orow[tx + 32 * q] = v;
            cs[q] += v;
            c2[q] = fmaf(v, v, c2[q]);
        }
    }
#pragma unroll
    for (int q = 0; q < 6; q++) {
        atomicAdd(&gsum[tx + 32 * q], cs[q]);
        atomicAdd(&gsq [tx + 32 * q], c2[q]);
    }
}

// ---------------------------------------------------------------------------
// Depthwise kernel-point conv, f32x2 over point-pairs, group-staged.
// One block = 192 threads (one per channel). Each group = 4 points (2 pairs):
//   phase 1: load neighbor indices + relative coords (64 threads)
//   phase 2: compute influence for all 4 points into shared, interleaved
//            [k][pair][2h+p] so LDS.128 yields packed (p0,p1) operands
//   phase 3: two barrier-free pair-phases: k-loop (FFMA2) + gather/aggregate
// Only 3 barriers per 4 points. BN1+ReLU fused at gather; BN2 stats out.
__global__ __launch_bounds__(192) void conv_kernel(
    const float* __restrict__ coord, const int* __restrict__ ref_idx,
    const float* __restrict__ kp, const float* __restrict__ tmp1,
    const float* __restrict__ st1, const float* __restrict__ Wk,
    float* __restrict__ out,
    float* __restrict__ gsum, float* __restrict__ gsq)
{
    __shared__ __align__(16) float s_wk[NK * CH];          // 33 KB
    __shared__ __align__(16) float s_infl[NK][2][2 * NH];  // [k][pair][2h+p] 11 KB
    __shared__ int   s_ref[4][NH];
    __shared__ float s_nb[4][NH][3];
    __shared__ float s_kp[NK * 3];

    const int tid = threadIdx.x;   // channel index
    for (int i = tid; i < NK * CH; i += 192) s_wk[i] = Wk[i];
    for (int i = tid; i < NK * 3;  i += 192) s_kp[i] = kp[i];

    const float s1c = st1[tid];
    const float t1c = st1[CH + tid];
    float lsum = 0.f, lsq = 0.f;

    const int base = blockIdx.x * (4 * GROUPS);
    for (int g = 0; g < GROUPS; g++) {
        const int n0 = base + g * 4;
        __syncthreads();   // previous group done reading s_ref / s_infl
        // --- phase 1: neighbor indices + relative coords (4 pts x 16 h) ---
        if (tid < 64) {
            int p = tid >> 4;
            int h = tid & 15;
            int n = n0 + p;
            int r = ref_idx[n * NH + h];
            s_ref[p][h] = r;
            s_nb[p][h][0] = coord[r * 3 + 0] - coord[n * 3 + 0];
            s_nb[p][h][1] = coord[r * 3 + 1] - coord[n * 3 + 1];
            s_nb[p][h][2] = coord[r * 3 + 2] - coord[n * 3 + 2];
        }
        __syncthreads();
        // --- phase 2: influence for all 4 points (43*16*4 = 2752 items) ---
        for (int i = tid; i < NK * NH * 4; i += 192) {
            int k   = i >> 6;          // 64 items per k
            int rem = i & 63;
            int p   = rem >> 4;
            int h   = rem & 15;
            float dx = s_nb[p][h][0] - s_kp[k * 3 + 0];
            float dy = s_nb[p][h][1] - s_kp[k * 3 + 1];
            float dz = s_nb[p][h][2] - s_kp[k * 3 + 2];
            float d  = fast_sqrt(fmaf(dx, dx, fmaf(dy, dy, dz * dz)));
            s_infl[k][p >> 1][2 * h + (p & 1)] = fmaxf(1.0f - d, 0.0f); // SIGMA==1
        }
        __syncthreads();

        // --- phase 3: two pair-phases, no barriers ---
#pragma unroll
        for (int pr = 0; pr < 2; pr++) {
            ull acc[NH];
#pragma unroll
            for (int h = 0; h < NH; h++) acc[h] = 0ull;
#pragma unroll
            for (int k = 0; k < NK; k++) {
                float w = s_wk[k * CH + tid];
                ull w2 = pack2(w, w);
                const ulonglong2* ip = (const ulonglong2*)&s_infl[k][pr][0];
#pragma unroll
                for (int h2 = 0; h2 < 8; h2++) {
                    ulonglong2 u = ip[h2];   // LDS.128 broadcast: 2 packed pairs
                    ffma2(acc[2 * h2 + 0], u.x, w2);
                    ffma2(acc[2 * h2 + 1], u.y, w2);
                }
            }

            // gather fc1 rows (BN1+ReLU fused) and aggregate, both points
            const int pa = 2 * pr, pb = 2 * pr + 1;
            float o0 = 0.f, o1 = 0.f;
#pragma unroll
            for (int h = 0; h < NH; h++) {
                float2 a = unpack2(acc[h]);
                float x0 = __ldg(tmp1 + (size_t)s_ref[pa][h] * CH + tid);
                x0 = fmaxf(fmaf(x0, s1c, t1c), 0.f);
                o0 = fmaf(a.x, x0, o0);
                float x1 = __ldg(tmp1 + (size_t)s_ref[pb][h] * CH + tid);
                x1 = fmaxf(fmaf(x1, s1c, t1c), 0.f);
                o1 = fmaf(a.y, x1, o1);
            }
            out[(size_t)(n0 + pa) * CH + tid] = o0;
            out[(size_t)(n0 + pb) * CH + tid] = o1;
            lsum += o0 + o1;
            lsq  = fmaf(o0, o0, fmaf(o1, o1, lsq));
        }
    }
    atomicAdd(&gsum[tid], lsum);
    atomicAdd(&gsq [tid], lsq);
}

// ---------------------------------------------------------------------------
// feat_out = relu(identity + BN3(tmp3))   (vectorized float4)
__global__ __launch_bounds__(256) void apply3_kernel(
    const float4* __restrict__ idf, const float4* __restrict__ t3,
    const float* __restrict__ st, float4* __restrict__ outf)
{
    int i  = blockIdx.x * blockDim.x + threadIdx.x;   // < NPTS*CH/4
    int cq = i % (CH / 4);
    float4 s = *(const float4*)(st + cq * 4);
    float4 t = *(const float4*)(st + CH + cq * 4);
    float4 x = t3[i];
    float4 d = idf[i];
    float4 r;
    r.x = fmaxf(d.x + fmaf(x.x, s.x, t.x), 0.f);
    r.y = fmaxf(d.y + fmaf(x.y, s.y, t.y), 0.f);
    r.z = fmaxf(d.z + fmaf(x.z, s.z, t.z), 0.f);
    r.w = fmaxf(d.w + fmaf(x.w, s.w, t.w), 0.f);
    outf[i] = r;
}

// ---------------------------------------------------------------------------
extern "C" void kernel_launch(void* const* d_in, const int* in_sizes, int n_in,
                              void* d_out, int out_size)
{
    const float* coord   = (const float*)d_in[0];
    const float* feat    = (const float*)d_in[1];
    const int*   ref_idx = (const int*)  d_in[2];
    const float* kp      = (const float*)d_in[3];
    const float* W1      = (const float*)d_in[4];
    const float* Wk      = (const float*)d_in[5];
    const float* W3      = (const float*)d_in[6];
    const float* g1      = (const float*)d_in[7];
    const float* b1      = (const float*)d_in[8];
    const float* g2      = (const float*)d_in[9];
    const float* b2      = (const float*)d_in[10];
    const float* g3      = (const float*)d_in[11];
    const float* b3      = (const float*)d_in[12];
    float* out = (float*)d_out;

    float *tmp1, *tmp2, *tmp3, *featbuf, *stats, *st;
    cudaGetSymbolAddress((void**)&tmp1,    g_tmp1);
    cudaGetSymbolAddress((void**)&tmp2,    g_tmp2);
    cudaGetSymbolAddress((void**)&tmp3,    g_tmp3);
    cudaGetSymbolAddress((void**)&featbuf, g_featbuf);
    cudaGetSymbolAddress((void**)&stats,   g_stats);
    cudaGetSymbolAddress((void**)&st,      g_st);

    zero_stats_kernel<<<1, 256>>>(stats);

    const int NVEC = NPTS * CH / 4;             // 786432
    for (int i = 0; i < DEPTH; i++) {
        const float* fin_ = (i == 0) ? feat : featbuf;
        float* fout = (i == DEPTH - 1) ? out : featbuf;
        const int s0 = 3 * i + 0, s1 = 3 * i + 1, s2 = 3 * i + 2;

        // fc1 (+BN1 stats)
        gemm192_kernel<<<NPTS / 64, 256>>>(
            fin_, W1 + (size_t)i * CH * CH, tmp1, nullptr, 0,
            stats + s0 * 2 * CH, stats + s0 * 2 * CH + CH);
        fin_kernel<<<1, CH>>>(stats + s0 * 2 * CH, g1 + i * CH, b1 + i * CH,
                              st + s0 * 2 * CH);

        // KP depthwise conv (BN1+ReLU fused at gather; BN2 stats out)
        conv_kernel<<<NPTS / (4 * GROUPS), CH>>>(
            coord, ref_idx, kp, tmp1, st + s0 * 2 * CH,
            Wk + (size_t)i * NK * CH, tmp2,
            stats + s1 * 2 * CH, stats + s1 * 2 * CH + CH);
        fin_kernel<<<1, CH>>>(stats + s1 * 2 * CH, g2 + i * CH, b2 + i * CH,
                              st + s1 * 2 * CH);

        // fc3 (BN2+ReLU fused on A load; BN3 stats out)
        gemm192_kernel<<<NPTS / 64, 256>>>(
            tmp2, W3 + (size_t)i * CH * CH, tmp3, st + s1 * 2 * CH, 1,
            stats + s2 * 2 * CH, stats + s2 * 2 * CH + CH);
        fin_kernel<<<1, CH>>>(stats + s2 * 2 * CH, g3 + i * CH, b3 + i * CH,
                              st + s2 * 2 * CH);

        // skip + BN3 + ReLU
        apply3_kernel<<<NVEC / 256, 256>>>(
            (const float4*)fin_, (const float4*)tmp3, st + s2 * 2 * CH,
            (float4*)fout);
    }
}

// round 7
// speedup vs baseline: 1.2095x; 1.0051x over previous
#include <cuda_runtime.h>
#include <cuda_bf16.h>
#include <cstddef>

// Problem constants (fixed by the reference)
#define NPTS 16384
#define CH   192
#define NH   16
#define NK   43
#define DEPTH 2
#define BN_EPS 1e-5f
#define PTS_PER_BLK 32
#define NPAIRS 16        // pairs per conv block (2 points each)

typedef unsigned long long ull;

// ---------------- scratch (device globals; no allocation allowed) ----------
__device__ float g_tmp1[NPTS * CH];
__device__ float g_tmp2[NPTS * CH];
__device__ float g_tmp3[NPTS * CH];
__device__ float g_featbuf[NPTS * CH];
__device__ float g_stats[6 * 2 * CH];   // 6 stages x (sum[CH], sumsq[CH])
__device__ float g_st[6 * 2 * CH];      // 6 stages x (scale[CH], shift[CH])

// ---------------- f32x2 packed helpers -------------------------------------
__device__ __forceinline__ ull pack2(float x, float y) {
    ull r;
    asm("mov.b64 %0, {%1, %2};" : "=l"(r) : "f"(x), "f"(y));
    return r;
}
__device__ __forceinline__ void ffma2(ull& d, ull a, ull b) {
    asm("fma.rn.f32x2 %0, %1, %2, %0;" : "+l"(d) : "l"(a), "l"(b));
}
__device__ __forceinline__ float2 unpack2(ull v) {
    float2 r;
    asm("mov.b64 {%0, %1}, %2;" : "=f"(r.x), "=f"(r.y) : "l"(v));
    return r;
}
__device__ __forceinline__ float fast_sqrt(float x) {
    float r;
    asm("sqrt.approx.f32 %0, %1;" : "=f"(r) : "f"(x));
    return r;
}

// ---------------------------------------------------------------------------
__global__ void zero_stats_kernel(float* stats) {
    for (int i = threadIdx.x; i < 6 * 2 * CH; i += blockDim.x) stats[i] = 0.f;
}

// finalize BN: scale = g * rsqrt(var+eps), shift = b - mean*scale
__global__ void fin_kernel(const float* __restrict__ stats,
                           const float* __restrict__ g,
                           const float* __restrict__ b,
                           float* __restrict__ st) {
    int c = threadIdx.x;   // 192 threads
    float m = stats[c] * (1.0f / NPTS);
    float v = stats[CH + c] * (1.0f / NPTS) - m * m;
    float s = g[c] * rsqrtf(v + BN_EPS);
    st[c]      = s;
    st[CH + c] = b[c] - m * s;
}

// ---------------------------------------------------------------------------
// GEMM: out[N,192] = act(A)[N,192] @ W[192,192]  (scalar, near FFMA roofline).
// Optional fused BN+ReLU on A load. Accumulates per-channel sum / sumsq for
// the next BN. Block: 256 threads, 64x192 tile.
__global__ __launch_bounds__(256) void gemm192_kernel(
    const float* __restrict__ A, const float* __restrict__ W,
    float* __restrict__ out, const float* __restrict__ st_in, int fuse,
    float* __restrict__ gsum, float* __restrict__ gsq)
{
    __shared__ __align__(16) float sA[64][32];
    __shared__ __align__(16) float sB[32][192];

    const int tid = threadIdx.x;
    const int tx  = tid & 31;        // 0..31
    const int ty  = tid >> 5;        // 0..7
    const int row0 = blockIdx.x * 64;

    float acc[8][6];
#pragma unroll
    for (int r = 0; r < 8; r++)
#pragma unroll
        for (int q = 0; q < 6; q++) acc[r][q] = 0.f;

    for (int k0 = 0; k0 < 192; k0 += 32) {
        // --- load A tile (64x32) as float4, optional BN+ReLU transform ---
#pragma unroll
        for (int it = tid; it < 512; it += 256) {
            int r  = it >> 3;
            int kq = it & 7;
            float4 v = *(const float4*)(A + (size_t)(row0 + r) * CH + k0 + kq * 4);
            if (fuse) {
                float4 s = *(const float4*)(st_in + k0 + kq * 4);
                float4 t = *(const float4*)(st_in + CH + k0 + kq * 4);
                v.x = fmaxf(fmaf(v.x, s.x, t.x), 0.f);
                v.y = fmaxf(fmaf(v.y, s.y, t.y), 0.f);
                v.z = fmaxf(fmaf(v.z, s.z, t.z), 0.f);
                v.w = fmaxf(fmaf(v.w, s.w, t.w), 0.f);
            }
            *(float4*)&sA[r][kq * 4] = v;
        }
        // --- load B tile (32x192) ---
#pragma unroll
        for (int it = tid; it < 1536; it += 256) {
            int kk = it / 48;
            int cq = it - kk * 48;
            *(float4*)&sB[kk][cq * 4] =
                *(const float4*)(W + (size_t)(k0 + kk) * CH + cq * 4);
        }
        __syncthreads();

#pragma unroll
        for (int kk4 = 0; kk4 < 8; kk4++) {
            float4 av[8];
#pragma unroll
            for (int r = 0; r < 8; r++)
                av[r] = *(const float4*)&sA[ty * 8 + r][kk4 * 4];
#pragma unroll
            for (int j = 0; j < 4; j++) {
                float bv[6];
#pragma unroll
                for (int q = 0; q < 6; q++)
                    bv[q] = sB[kk4 * 4 + j][tx + 32 * q];
#pragma unroll
                for (int r = 0; r < 8; r++) {
                    float a = (j == 0) ? av[r].x : (j == 1) ? av[r].y
                            : (j == 2) ? av[r].z : av[r].w;
#pragma unroll
                    for (int q = 0; q < 6; q++)
                        acc[r][q] = fmaf(a, bv[q], acc[r][q]);
                }
            }
        }
        __syncthreads();
    }

    // --- write out + per-channel stats ---
    float cs[6], c2[6];
#pragma unroll
    for (int q = 0; q < 6; q++) { cs[q] = 0.f; c2[q] = 0.f; }
#pragma unroll
    for (int r = 0; r < 8; r++) {
        float* orow = out + (size_t)(row0 + ty * 8 + r) * CH;
#pragma unroll
        for (int q = 0; q < 6; q++) {
            float v = acc[r][q];
            orow[tx + 32 * q] = v;
            cs[q] += v;
            c2[q] = fmaf(v, v, c2[q]);
        }
    }
#pragma unroll
    for (int q = 0; q < 6; q++) {
        atomicAdd(&gsum[tx + 32 * q], cs[q]);
        atomicAdd(&gsq [tx + 32 * q], c2[q]);
    }
}

// ---------------------------------------------------------------------------
// Depthwise kernel-point conv, software-pipelined over point-pairs.
// One block = 192 threads (one per channel), 32 points (16 pairs).
// Iteration p runs three INDEPENDENT stages (disjoint smem buffers), then one
// barrier:
//   L(p+2): load neighbor relative coords into nb[p&1]        (32 threads)
//   I(p+1): influence for pair p+1 into infl[(p+1)&1]         (all threads)
//   C(p)  : f32x2 k-loop + gather/aggregate from infl[p&1]    (all threads)
// Neighbor indices for all 32 points are staged once in the prologue.
__global__ __launch_bounds__(192, 4) void conv_kernel(
    const float* __restrict__ coord, const int* __restrict__ ref_idx,
    const float* __restrict__ kp, const float* __restrict__ tmp1,
    const float* __restrict__ st1, const float* __restrict__ Wk,
    float* __restrict__ out,
    float* __restrict__ gsum, float* __restrict__ gsq)
{
    __shared__ __align__(16) float s_wk[NK * CH];        // 33024 B
    __shared__ __align__(16) float s_infl[2][NK][32];    // 11008 B, row=128B
    __shared__ int   s_ref[PTS_PER_BLK][NH];             // 2048 B
    __shared__ float s_nb[2][2][NH][3];                  // 768 B
    __shared__ float s_kp[NK * 3];                       // 516 B

    const int tid  = threadIdx.x;   // channel index
    const int base = blockIdx.x * PTS_PER_BLK;

    for (int i = tid; i < NK * CH; i += 192) s_wk[i] = Wk[i];
    for (int i = tid; i < NK * 3;  i += 192) s_kp[i] = kp[i];
    for (int i = tid; i < PTS_PER_BLK * NH; i += 192)
        s_ref[i >> 4][i & 15] = ref_idx[(base + (i >> 4)) * NH + (i & 15)];
    __syncthreads();   // s_ref ready for L stages

    // L(0), L(1): relative coords for pairs 0 and 1 (points 0..3)
    if (tid < 64) {
        int pt = tid >> 4;          // 0..3
        int h  = tid & 15;
        int n  = base + pt;
        int r  = s_ref[pt][h];
        int buf = (pt >> 1) & 1;
        int sub = pt & 1;
        s_nb[buf][sub][h][0] = coord[r * 3 + 0] - coord[n * 3 + 0];
        s_nb[buf][sub][h][1] = coord[r * 3 + 1] - coord[n * 3 + 1];
        s_nb[buf][sub][h][2] = coord[r * 3 + 2] - coord[n * 3 + 2];
    }
    __syncthreads();   // nb(0), nb(1) ready

    // I(0): influence for pair 0
    for (int i = tid; i < NK * 32; i += 192) {
        int k   = i >> 5;
        int rem = i & 31;
        int h   = rem >> 1;
        int p   = rem & 1;
        float dx = s_nb[0][p][h][0] - s_kp[k * 3 + 0];
        float dy = s_nb[0][p][h][1] - s_kp[k * 3 + 1];
        float dz = s_nb[0][p][h][2] - s_kp[k * 3 + 2];
        float d  = fast_sqrt(fmaf(dx, dx, fmaf(dy, dy, dz * dz)));
        s_infl[0][k][rem] = fmaxf(1.0f - d, 0.0f);   // SIGMA == 1
    }
    __syncthreads();   // infl(0) ready

    const float s1c = st1[tid];
    const float t1c = st1[CH + tid];
    float lsum = 0.f, lsq = 0.f;

    for (int pr = 0; pr < NPAIRS; pr++) {
        // --- L(pr+2): next-next pair's relative coords into nb[pr&1] ---
        if (pr + 2 < NPAIRS && tid < 32) {
            int p  = tid >> 4;      // 0/1 within pair
            int h  = tid & 15;
            int pt = (pr + 2) * 2 + p;
            int n  = base + pt;
            int r  = s_ref[pt][h];
            s_nb[pr & 1][p][h][0] = coord[r * 3 + 0] - coord[n * 3 + 0];
            s_nb[pr & 1][p][h][1] = coord[r * 3 + 1] - coord[n * 3 + 1];
            s_nb[pr & 1][p][h][2] = coord[r * 3 + 2] - coord[n * 3 + 2];
        }
        // --- I(pr+1): next pair's influence into infl[(pr+1)&1] ---
        if (pr + 1 < NPAIRS) {
            const int b1 = (pr + 1) & 1;
            for (int i = tid; i < NK * 32; i += 192) {
                int k   = i >> 5;
                int rem = i & 31;
                int h   = rem >> 1;
                int p   = rem & 1;
                float dx = s_nb[b1][p][h][0] - s_kp[k * 3 + 0];
                float dy = s_nb[b1][p][h][1] - s_kp[k * 3 + 1];
                float dz = s_nb[b1][p][h][2] - s_kp[k * 3 + 2];
                float d  = fast_sqrt(fmaf(dx, dx, fmaf(dy, dy, dz * dz)));
                s_infl[b1][k][rem] = fmaxf(1.0f - d, 0.0f);
            }
        }

        // --- C(pr): k-loop (FFMA2) + gather/aggregate ---
        const int bc = pr & 1;
        ull acc[NH];
#pragma unroll
        for (int h = 0; h < NH; h++) acc[h] = 0ull;
#pragma unroll
        for (int k = 0; k < NK; k++) {
            float w = s_wk[k * CH + tid];
            ull w2 = pack2(w, w);
            const ulonglong2* ip = (const ulonglong2*)&s_infl[bc][k][0];
#pragma unroll
            for (int h2 = 0; h2 < 8; h2++) {
                ulonglong2 u = ip[h2];   // LDS.128 broadcast: 2 packed pairs
                ffma2(acc[2 * h2 + 0], u.x, w2);
                ffma2(acc[2 * h2 + 1], u.y, w2);
            }
        }

        const int pta = pr * 2, ptb = pr * 2 + 1;
        float o0 = 0.f, o1 = 0.f;
#pragma unroll
        for (int h = 0; h < NH; h++) {
            float2 a = unpack2(acc[h]);
            float x0 = __ldg(tmp1 + (size_t)s_ref[pta][h] * CH + tid);
            x0 = fmaxf(fmaf(x0, s1c, t1c), 0.f);
            o0 = fmaf(a.x, x0, o0);
            float x1 = __ldg(tmp1 + (size_t)s_ref[ptb][h] * CH + tid);
            x1 = fmaxf(fmaf(x1, s1c, t1c), 0.f);
            o1 = fmaf(a.y, x1, o1);
        }
        out[(size_t)(base + pta) * CH + tid] = o0;
        out[(size_t)(base + ptb) * CH + tid] = o1;
        lsum += o0 + o1;
        lsq  = fmaf(o0, o0, fmaf(o1, o1, lsq));

        __syncthreads();   // one barrier per pair
    }
    atomicAdd(&gsum[tid], lsum);
    atomicAdd(&gsq [tid], lsq);
}

// ---------------------------------------------------------------------------
// feat_out = relu(identity + BN3(tmp3))   (vectorized float4)
__global__ __launch_bounds__(256) void apply3_kernel(
    const float4* __restrict__ idf, const float4* __restrict__ t3,
    const float* __restrict__ st, float4* __restrict__ outf)
{
    int i  = blockIdx.x * blockDim.x + threadIdx.x;   // < NPTS*CH/4
    int cq = i % (CH / 4);
    float4 s = *(const float4*)(st + cq * 4);
    float4 t = *(const float4*)(st + CH + cq * 4);
    float4 x = t3[i];
    float4 d = idf[i];
    float4 r;
    r.x = fmaxf(d.x + fmaf(x.x, s.x, t.x), 0.f);
    r.y = fmaxf(d.y + fmaf(x.y, s.y, t.y), 0.f);
    r.z = fmaxf(d.z + fmaf(x.z, s.z, t.z), 0.f);
    r.w = fmaxf(d.w + fmaf(x.w, s.w, t.w), 0.f);
    outf[i] = r;
}

// ---------------------------------------------------------------------------
extern "C" void kernel_launch(void* const* d_in, const int* in_sizes, int n_in,
                              void* d_out, int out_size)
{
    const float* coord   = (const float*)d_in[0];
    const float* feat    = (const float*)d_in[1];
    const int*   ref_idx = (const int*)  d_in[2];
    const float* kp      = (const float*)d_in[3];
    const float* W1      = (const float*)d_in[4];
    const float* Wk      = (const float*)d_in[5];
    const float* W3      = (const float*)d_in[6];
    const float* g1      = (const float*)d_in[7];
    const float* b1      = (const float*)d_in[8];
    const float* g2      = (const float*)d_in[9];
    const float* b2      = (const float*)d_in[10];
    const float* g3      = (const float*)d_in[11];
    const float* b3      = (const float*)d_in[12];
    float* out = (float*)d_out;

    float *tmp1, *tmp2, *tmp3, *featbuf, *stats, *st;
    cudaGetSymbolAddress((void**)&tmp1,    g_tmp1);
    cudaGetSymbolAddress((void**)&tmp2,    g_tmp2);
    cudaGetSymbolAddress((void**)&tmp3,    g_tmp3);
    cudaGetSymbolAddress((void**)&featbuf, g_featbuf);
    cudaGetSymbolAddress((void**)&stats,   g_stats);
    cudaGetSymbolAddress((void**)&st,      g_st);

    zero_stats_kernel<<<1, 256>>>(stats);

    const int NVEC = NPTS * CH / 4;             // 786432
    for (int i = 0; i < DEPTH; i++) {
        const float* fin_ = (i == 0) ? feat : featbuf;
        float* fout = (i == DEPTH - 1) ? out : featbuf;
        const int s0 = 3 * i + 0, s1 = 3 * i + 1, s2 = 3 * i + 2;

        // fc1 (+BN1 stats)
        gemm192_kernel<<<NPTS / 64, 256>>>(
            fin_, W1 + (size_t)i * CH * CH, tmp1, nullptr, 0,
            stats + s0 * 2 * CH, stats + s0 * 2 * CH + CH);
        fin_kernel<<<1, CH>>>(stats + s0 * 2 * CH, g1 + i * CH, b1 + i * CH,
                              st + s0 * 2 * CH);

        // KP depthwise conv (BN1+ReLU fused at gather; BN2 stats out)
        conv_kernel<<<NPTS / PTS_PER_BLK, CH>>>(
            coord, ref_idx, kp, tmp1, st + s0 * 2 * CH,
            Wk + (size_t)i * NK * CH, tmp2,
            stats + s1 * 2 * CH, stats + s1 * 2 * CH + CH);
        fin_kernel<<<1, CH>>>(stats + s1 * 2 * CH, g2 + i * CH, b2 + i * CH,
                              st + s1 * 2 * CH);

        // fc3 (BN2+ReLU fused on A load; BN3 stats out)
        gemm192_kernel<<<NPTS / 64, 256>>>(
            tmp2, W3 + (size_t)i * CH * CH, tmp3, st + s1 * 2 * CH, 1,
            stats + s2 * 2 * CH, stats + s2 * 2 * CH + CH);
        fin_kernel<<<1, CH>>>(stats + s2 * 2 * CH, g3 + i * CH, b3 + i * CH,
                              st + s2 * 2 * CH);

        // skip + BN3 + ReLU
        apply3_kernel<<<NVEC / 256, 256>>>(
            (const float4*)fin_, (const float4*)tmp3, st + s2 * 2 * CH,
            (float4*)fout);
    }
}

// round 9
// speedup vs baseline: 1.3553x; 1.1205x over previous
#include <cuda_runtime.h>
#include <cuda_bf16.h>
#include <cstddef>

// Problem constants (fixed by the reference)
#define NPTS 16384
#define CH   192
#define NH   16
#define NK   43
#define DEPTH 2
#define BN_EPS 1e-5f
#define PTS_PER_BLK 32
#define NPAIRS 16        // pairs per conv block (2 points each)

typedef unsigned long long ull;

// ---------------- scratch (device globals; no allocation allowed) ----------
__device__ float g_tmp1[NPTS * CH];
__device__ float g_tmp2[NPTS * CH];
__device__ float g_tmp3[NPTS * CH];
__device__ float g_featbuf[NPTS * CH];
__device__ float g_stats[6 * 2 * CH];   // 6 stages x (sum[CH], sumsq[CH])
__device__ float g_st[6 * 2 * CH];      // 6 stages x (scale[CH], shift[CH])

// ---------------- f32x2 packed helpers -------------------------------------
__device__ __forceinline__ ull pack2(float x, float y) {
    ull r;
    asm("mov.b64 %0, {%1, %2};" : "=l"(r) : "f"(x), "f"(y));
    return r;
}
__device__ __forceinline__ void ffma2(ull& d, ull a, ull b) {
    asm("fma.rn.f32x2 %0, %1, %2, %0;" : "+l"(d) : "l"(a), "l"(b));
}
__device__ __forceinline__ float2 unpack2(ull v) {
    float2 r;
    asm("mov.b64 {%0, %1}, %2;" : "=f"(r.x), "=f"(r.y) : "l"(v));
    return r;
}
__device__ __forceinline__ float fast_sqrt(float x) {
    float r;
    asm("sqrt.approx.f32 %0, %1;" : "=f"(r) : "f"(x));
    return r;
}

// ---------------------------------------------------------------------------
__global__ void zero_stats_kernel(float* stats) {
    for (int i = threadIdx.x; i < 6 * 2 * CH; i += blockDim.x) stats[i] = 0.f;
}

// finalize BN: scale = g * rsqrt(var+eps), shift = b - mean*scale
__global__ void fin_kernel(const float* __restrict__ stats,
                           const float* __restrict__ g,
                           const float* __restrict__ b,
                           float* __restrict__ st) {
    int c = threadIdx.x;   // 192 threads
    float m = stats[c] * (1.0f / NPTS);
    float v = stats[CH + c] * (1.0f / NPTS) - m * m;
    float s = g[c] * rsqrtf(v + BN_EPS);
    st[c]      = s;
    st[CH + c] = b[c] - m * s;
}

// ---------------------------------------------------------------------------
// GEMM: out[N,192] = act(A)[N,192] @ W[192,192]  (scalar, near FFMA roofline).
// Optional fused BN+ReLU on A load. Accumulates per-channel sum / sumsq for
// the next BN. Block: 256 threads, 64x192 tile.
__global__ __launch_bounds__(256) void gemm192_kernel(
    const float* __restrict__ A, const float* __restrict__ W,
    float* __restrict__ out, const float* __restrict__ st_in, int fuse,
    float* __restrict__ gsum, float* __restrict__ gsq)
{
    __shared__ __align__(16) float sA[64][32];
    __shared__ __align__(16) float sB[32][192];

    const int tid = threadIdx.x;
    const int tx  = tid & 31;        // 0..31
    const int ty  = tid >> 5;        // 0..7
    const int row0 = blockIdx.x * 64;

    float acc[8][6];
#pragma unroll
    for (int r = 0; r < 8; r++)
#pragma unroll
        for (int q = 0; q < 6; q++) acc[r][q] = 0.f;

    for (int k0 = 0; k0 < 192; k0 += 32) {
        // --- load A tile (64x32) as float4, optional BN+ReLU transform ---
#pragma unroll
        for (int it = tid; it < 512; it += 256) {
            int r  = it >> 3;
            int kq = it & 7;
            float4 v = *(const float4*)(A + (size_t)(row0 + r) * CH + k0 + kq * 4);
            if (fuse) {
                float4 s = *(const float4*)(st_in + k0 + kq * 4);
                float4 t = *(const float4*)(st_in + CH + k0 + kq * 4);
                v.x = fmaxf(fmaf(v.x, s.x, t.x), 0.f);
                v.y = fmaxf(fmaf(v.y, s.y, t.y), 0.f);
                v.z = fmaxf(fmaf(v.z, s.z, t.z), 0.f);
                v.w = fmaxf(fmaf(v.w, s.w, t.w), 0.f);
            }
            *(float4*)&sA[r][kq * 4] = v;
        }
        // --- load B tile (32x192) ---
#pragma unroll
        for (int it = tid; it < 1536; it += 256) {
            int kk = it / 48;
            int cq = it - kk * 48;
            *(float4*)&sB[kk][cq * 4] =
                *(const float4*)(W + (size_t)(k0 + kk) * CH + cq * 4);
        }
        __syncthreads();

#pragma unroll
        for (int kk4 = 0; kk4 < 8; kk4++) {
            float4 av[8];
#pragma unroll
            for (int r = 0; r < 8; r++)
                av[r] = *(const float4*)&sA[ty * 8 + r][kk4 * 4];
#pragma unroll
            for (int j = 0; j < 4; j++) {
                float bv[6];
#pragma unroll
                for (int q = 0; q < 6; q++)
                    bv[q] = sB[kk4 * 4 + j][tx + 32 * q];
#pragma unroll
                for (int r = 0; r < 8; r++) {
                    float a = (j == 0) ? av[r].x : (j == 1) ? av[r].y
                            : (j == 2) ? av[r].z : av[r].w;
#pragma unroll
                    for (int q = 0; q < 6; q++)
                        acc[r][q] = fmaf(a, bv[q], acc[r][q]);
                }
            }
        }
        __syncthreads();
    }

    // --- write out + per-channel stats ---
    float cs[6], c2[6];
#pragma unroll
    for (int q = 0; q < 6; q++) { cs[q] = 0.f; c2[q] = 0.f; }
#pragma unroll
    for (int r = 0; r < 8; r++) {
        float* orow = out + (size_t)(row0 + ty * 8 + r) * CH;
#pragma unroll
        for (int q = 0; q < 6; q++) {
            float v = acc[r][q];
            orow[tx + 32 * q] = v;
            cs[q] += v;
            c2[q] = fmaf(v, v, c2[q]);
        }
    }
#pragma unroll
    for (int q = 0; q < 6; q++) {
        atomicAdd(&gsum[tx + 32 * q], cs[q]);
        atomicAdd(&gsq [tx + 32 * q], c2[q]);
    }
}

// ---------------------------------------------------------------------------
// Depthwise kernel-point conv, 2-D register-blocked.
// One block = 192 threads, 32 points (16 pairs). Thread (cg,hg) =
// (tid>>2, tid&3) owns 4 channels (cg*4..+3) x 4 neighbors (hg*4..+3),
// with the 2 points of the pair packed in f32x2 lanes.
// Per-k loads: 1 LDS.128 (w, 4 ch) + 2 LDS.128 (infl, 8 floats) for
// 16 FFMA2 — 3x fewer LDS than the per-channel mapping (L1-bound before).
// h-sum completed by a 2-step shfl_xor over the 4-lane quad.
// BN1+ReLU fused at gather; BN2 stats accumulated (hg==0 lanes only).
__global__ __launch_bounds__(192, 4) void conv_kernel(
    const float* __restrict__ coord, const int* __restrict__ ref_idx,
    const float* __restrict__ kp, const float* __restrict__ tmp1,
    const float* __restrict__ st1, const float* __restrict__ Wk,
    float* __restrict__ out,
    float* __restrict__ gsum, float* __restrict__ gsq)
{
    __shared__ __align__(16) float s_wk[NK * CH];        // 33024 B
    __shared__ __align__(16) float s_infl[NK][32];       // 5504 B, [k][2h+p]
    __shared__ int   s_ref[2][NH];
    __shared__ float s_nb[2][NH][3];
    __shared__ float s_kp[NK * 3];

    const int tid  = threadIdx.x;
    const int cg   = tid >> 2;       // channel group 0..47
    const int hg   = tid & 3;        // h group 0..3
    const int base = blockIdx.x * PTS_PER_BLK;

    for (int i = tid; i < NK * CH; i += 192) s_wk[i] = Wk[i];
    for (int i = tid; i < NK * 3;  i += 192) s_kp[i] = kp[i];

    // BN1 consts for my 4 channels
    const float4 s4 = *(const float4*)(st1 + cg * 4);
    const float4 t4 = *(const float4*)(st1 + CH + cg * 4);

    float ls[4] = {0.f, 0.f, 0.f, 0.f};
    float lq[4] = {0.f, 0.f, 0.f, 0.f};

#pragma unroll 1
    for (int pr = 0; pr < NPAIRS; pr++) {
        const int n0 = base + 2 * pr;
        __syncthreads();   // previous iteration done reading s_infl / s_ref
        // --- neighbor indices + relative coords for the 2 points ---
        if (tid < 32) {
            int p = tid >> 4;
            int h = tid & 15;
            int n = n0 + p;
            int r = ref_idx[n * NH + h];
            s_ref[p][h] = r;
            s_nb[p][h][0] = coord[r * 3 + 0] - coord[n * 3 + 0];
            s_nb[p][h][1] = coord[r * 3 + 1] - coord[n * 3 + 1];
            s_nb[p][h][2] = coord[r * 3 + 2] - coord[n * 3 + 2];
        }
        __syncthreads();
        // --- influence [k][2h+p] ---
        for (int i = tid; i < NK * 32; i += 192) {
            int k   = i >> 5;
            int rem = i & 31;
            int h   = rem >> 1;
            int p   = rem & 1;
            float dx = s_nb[p][h][0] - s_kp[k * 3 + 0];
            float dy = s_nb[p][h][1] - s_kp[k * 3 + 1];
            float dz = s_nb[p][h][2] - s_kp[k * 3 + 2];
            float d  = fast_sqrt(fmaf(dx, dx, fmaf(dy, dy, dz * dz)));
            s_infl[k][rem] = fmaxf(1.0f - d, 0.0f);   // SIGMA == 1
        }
        __syncthreads();

        // --- k-loop: acc[j_h][j_c] (f32x2 over points) ---
        ull acc[4][4];
#pragma unroll
        for (int j = 0; j < 4; j++)
#pragma unroll
            for (int c = 0; c < 4; c++) acc[j][c] = 0ull;

#pragma unroll 43
        for (int k = 0; k < NK; k++) {
            const float4 wv = *(const float4*)&s_wk[k * CH + cg * 4];
            ull w0 = pack2(wv.x, wv.x);
            ull w1 = pack2(wv.y, wv.y);
            ull w2 = pack2(wv.z, wv.z);
            ull w3 = pack2(wv.w, wv.w);
            const ulonglong2 ua = *(const ulonglong2*)&s_infl[k][hg * 8];
            const ulonglong2 ub = *(const ulonglong2*)&s_infl[k][hg * 8 + 4];
            ffma2(acc[0][0], ua.x, w0); ffma2(acc[0][1], ua.x, w1);
            ffma2(acc[0][2], ua.x, w2); ffma2(acc[0][3], ua.x, w3);
            ffma2(acc[1][0], ua.y, w0); ffma2(acc[1][1], ua.y, w1);
            ffma2(acc[1][2], ua.y, w2); ffma2(acc[1][3], ua.y, w3);
            ffma2(acc[2][0], ub.x, w0); ffma2(acc[2][1], ub.x, w1);
            ffma2(acc[2][2], ub.x, w2); ffma2(acc[2][3], ub.x, w3);
            ffma2(acc[3][0], ub.y, w0); ffma2(acc[3][1], ub.y, w1);
            ffma2(acc[3][2], ub.y, w2); ffma2(acc[3][3], ub.y, w3);
        }

        // --- gather fc1 rows (BN1+ReLU fused, LDG.128) + partial h-sum ---
        float po0[4] = {0.f, 0.f, 0.f, 0.f};   // point 0
        float po1[4] = {0.f, 0.f, 0.f, 0.f};   // point 1
#pragma unroll
        for (int j = 0; j < 4; j++) {
            int h = hg * 4 + j;
            float4 x0 = *(const float4*)(tmp1 + (size_t)s_ref[0][h] * CH + cg * 4);
            float4 x1 = *(const float4*)(tmp1 + (size_t)s_ref[1][h] * CH + cg * 4);
            x0.x = fmaxf(fmaf(x0.x, s4.x, t4.x), 0.f);
            x0.y = fmaxf(fmaf(x0.y, s4.y, t4.y), 0.f);
            x0.z = fmaxf(fmaf(x0.z, s4.z, t4.z), 0.f);
            x0.w = fmaxf(fmaf(x0.w, s4.w, t4.w), 0.f);
            x1.x = fmaxf(fmaf(x1.x, s4.x, t4.x), 0.f);
            x1.y = fmaxf(fmaf(x1.y, s4.y, t4.y), 0.f);
            x1.z = fmaxf(fmaf(x1.z, s4.z, t4.z), 0.f);
            x1.w = fmaxf(fmaf(x1.w, s4.w, t4.w), 0.f);
            float2 a0 = unpack2(acc[j][0]);
            float2 a1 = unpack2(acc[j][1]);
            float2 a2 = unpack2(acc[j][2]);
            float2 a3 = unpack2(acc[j][3]);
            po0[0] = fmaf(a0.x, x0.x, po0[0]); po1[0] = fmaf(a0.y, x1.x, po1[0]);
            po0[1] = fmaf(a1.x, x0.y, po0[1]); po1[1] = fmaf(a1.y, x1.y, po1[1]);
            po0[2] = fmaf(a2.x, x0.z, po0[2]); po1[2] = fmaf(a2.y, x1.z, po1[2]);
            po0[3] = fmaf(a3.x, x0.w, po0[3]); po1[3] = fmaf(a3.y, x1.w, po1[3]);
        }

        // --- quad reduction over hg (lanes tid&3) ---
#pragma unroll
        for (int c = 0; c < 4; c++) {
            po0[c] += __shfl_xor_sync(0xffffffffu, po0[c], 1);
            po0[c] += __shfl_xor_sync(0xffffffffu, po0[c], 2);
            po1[c] += __shfl_xor_sync(0xffffffffu, po1[c], 1);
            po1[c] += __shfl_xor_sync(0xffffffffu, po1[c], 2);
        }

        if (hg == 0) {
            float4 o0 = make_float4(po0[0], po0[1], po0[2], po0[3]);
            float4 o1 = make_float4(po1[0], po1[1], po1[2], po1[3]);
            *(float4*)(out + (size_t)n0 * CH + cg * 4)       = o0;
            *(float4*)(out + (size_t)(n0 + 1) * CH + cg * 4) = o1;
#pragma unroll
            for (int c = 0; c < 4; c++) {
                ls[c] += po0[c] + po1[c];
                lq[c] = fmaf(po0[c], po0[c], fmaf(po1[c], po1[c], lq[c]));
            }
        }
    }
    if (hg == 0) {
#pragma unroll
        for (int c = 0; c < 4; c++) {
            atomicAdd(&gsum[cg * 4 + c], ls[c]);
            atomicAdd(&gsq [cg * 4 + c], lq[c]);
        }
    }
}

// ---------------------------------------------------------------------------
// feat_out = relu(identity + BN3(tmp3))   (vectorized float4)
__global__ __launch_bounds__(256) void apply3_kernel(
    const float4* __restrict__ idf, const float4* __restrict__ t3,
    const float* __restrict__ st, float4* __restrict__ outf)
{
    int i  = blockIdx.x * blockDim.x + threadIdx.x;   // < NPTS*CH/4
    int cq = i % (CH / 4);
    float4 s = *(const float4*)(st + cq * 4);
    float4 t = *(const float4*)(st + CH + cq * 4);
    float4 x = t3[i];
    float4 d = idf[i];
    float4 r;
    r.x = fmaxf(d.x + fmaf(x.x, s.x, t.x), 0.f);
    r.y = fmaxf(d.y + fmaf(x.y, s.y, t.y), 0.f);
    r.z = fmaxf(d.z + fmaf(x.z, s.z, t.z), 0.f);
    r.w = fmaxf(d.w + fmaf(x.w, s.w, t.w), 0.f);
    outf[i] = r;
}

// ---------------------------------------------------------------------------
extern "C" void kernel_launch(void* const* d_in, const int* in_sizes, int n_in,
                              void* d_out, int out_size)
{
    const float* coord   = (const float*)d_in[0];
    const float* feat    = (const float*)d_in[1];
    const int*   ref_idx = (const int*)  d_in[2];
    const float* kp      = (const float*)d_in[3];
    const float* W1      = (const float*)d_in[4];
    const float* Wk      = (const float*)d_in[5];
    const float* W3      = (const float*)d_in[6];
    const float* g1      = (const float*)d_in[7];
    const float* b1      = (const float*)d_in[8];
    const float* g2      = (const float*)d_in[9];
    const float* b2      = (const float*)d_in[10];
    const float* g3      = (const float*)d_in[11];
    const float* b3      = (const float*)d_in[12];
    float* out = (float*)d_out;

    float *tmp1, *tmp2, *tmp3, *featbuf, *stats, *st;
    cudaGetSymbolAddress((void**)&tmp1,    g_tmp1);
    cudaGetSymbolAddress((void**)&tmp2,    g_tmp2);
    cudaGetSymbolAddress((void**)&tmp3,    g_tmp3);
    cudaGetSymbolAddress((void**)&featbuf, g_featbuf);
    cudaGetSymbolAddress((void**)&stats,   g_stats);
    cudaGetSymbolAddress((void**)&st,      g_st);

    zero_stats_kernel<<<1, 256>>>(stats);

    const int NVEC = NPTS * CH / 4;             // 786432
    for (int i = 0; i < DEPTH; i++) {
        const float* fin_ = (i == 0) ? feat : featbuf;
        float* fout = (i == DEPTH - 1) ? out : featbuf;
        const int s0 = 3 * i + 0, s1 = 3 * i + 1, s2 = 3 * i + 2;

        // fc1 (+BN1 stats)
        gemm192_kernel<<<NPTS / 64, 256>>>(
            fin_, W1 + (size_t)i * CH * CH, tmp1, nullptr, 0,
            stats + s0 * 2 * CH, stats + s0 * 2 * CH + CH);
        fin_kernel<<<1, CH>>>(stats + s0 * 2 * CH, g1 + i * CH, b1 + i * CH,
                              st + s0 * 2 * CH);

        // KP depthwise conv (BN1+ReLU fused at gather; BN2 stats out)
        conv_kernel<<<NPTS / PTS_PER_BLK, CH>>>(
            coord, ref_idx, kp, tmp1, st + s0 * 2 * CH,
            Wk + (size_t)i * NK * CH, tmp2,
            stats + s1 * 2 * CH, stats + s1 * 2 * CH + CH);
        fin_kernel<<<1, CH>>>(stats + s1 * 2 * CH, g2 + i * CH, b2 + i * CH,
                              st + s1 * 2 * CH);

        // fc3 (BN2+ReLU fused on A load; BN3 stats out)
        gemm192_kernel<<<NPTS / 64, 256>>>(
            tmp2, W3 + (size_t)i * CH * CH, tmp3, st + s1 * 2 * CH, 1,
            stats + s2 * 2 * CH, stats + s2 * 2 * CH + CH);
        fin_kernel<<<1, CH>>>(stats + s2 * 2 * CH, g3 + i * CH, b3 + i * CH,
                              st + s2 * 2 * CH);

        // skip + BN3 + ReLU
        apply3_kernel<<<NVEC / 256, 256>>>(
            (const float4*)fin_, (const float4*)tmp3, st + s2 * 2 * CH,
            (float4*)fout);
    }
}

// round 10
// speedup vs baseline: 1.3668x; 1.0085x over previous
#include <cuda_runtime.h>
#include <cuda_bf16.h>
#include <cstddef>

// Problem constants (fixed by the reference)
#define NPTS 16384
#define CH   192
#define NH   16
#define NK   43
#define DEPTH 2
#define BN_EPS 1e-5f
#define PTS_PER_BLK 32
#define NPHASE 8         // phases per conv block, 4 points (2 pairs) each

typedef unsigned long long ull;

// ---------------- scratch (device globals; no allocation allowed) ----------
__device__ float g_tmp1[NPTS * CH];
__device__ float g_tmp2[NPTS * CH];
__device__ float g_tmp3[NPTS * CH];
__device__ float g_featbuf[NPTS * CH];
__device__ float g_stats[6 * 2 * CH];   // 6 stages x (sum[CH], sumsq[CH])
__device__ float g_st[6 * 2 * CH];      // 6 stages x (scale[CH], shift[CH])

// ---------------- f32x2 packed helpers -------------------------------------
__device__ __forceinline__ ull pack2(float x, float y) {
    ull r;
    asm("mov.b64 %0, {%1, %2};" : "=l"(r) : "f"(x), "f"(y));
    return r;
}
__device__ __forceinline__ void ffma2(ull& d, ull a, ull b) {
    asm("fma.rn.f32x2 %0, %1, %2, %0;" : "+l"(d) : "l"(a), "l"(b));
}
__device__ __forceinline__ float2 unpack2(ull v) {
    float2 r;
    asm("mov.b64 {%0, %1}, %2;" : "=f"(r.x), "=f"(r.y) : "l"(v));
    return r;
}
__device__ __forceinline__ float fast_sqrt(float x) {
    float r;
    asm("sqrt.approx.f32 %0, %1;" : "=f"(r) : "f"(x));
    return r;
}

// ---------------------------------------------------------------------------
__global__ void zero_stats_kernel(float* stats) {
    for (int i = threadIdx.x; i < 6 * 2 * CH; i += blockDim.x) stats[i] = 0.f;
}

// finalize BN: scale = g * rsqrt(var+eps), shift = b - mean*scale
__global__ void fin_kernel(const float* __restrict__ stats,
                           const float* __restrict__ g,
                           const float* __restrict__ b,
                           float* __restrict__ st) {
    int c = threadIdx.x;   // 192 threads
    float m = stats[c] * (1.0f / NPTS);
    float v = stats[CH + c] * (1.0f / NPTS) - m * m;
    float s = g[c] * rsqrtf(v + BN_EPS);
    st[c]      = s;
    st[CH + c] = b[c] - m * s;
}

// ---------------------------------------------------------------------------
// GEMM: out[N,192] = act(A)[N,192] @ W[192,192]  (scalar, near FFMA roofline).
// Optional fused BN+ReLU on A load. Accumulates per-channel sum / sumsq for
// the next BN. Block: 256 threads, 64x192 tile.
__global__ __launch_bounds__(256) void gemm192_kernel(
    const float* __restrict__ A, const float* __restrict__ W,
    float* __restrict__ out, const float* __restrict__ st_in, int fuse,
    float* __restrict__ gsum, float* __restrict__ gsq)
{
    __shared__ __align__(16) float sA[64][32];
    __shared__ __align__(16) float sB[32][192];

    const int tid = threadIdx.x;
    const int tx  = tid & 31;        // 0..31
    const int ty  = tid >> 5;        // 0..7
    const int row0 = blockIdx.x * 64;

    float acc[8][6];
#pragma unroll
    for (int r = 0; r < 8; r++)
#pragma unroll
        for (int q = 0; q < 6; q++) acc[r][q] = 0.f;

    for (int k0 = 0; k0 < 192; k0 += 32) {
        // --- load A tile (64x32) as float4, optional BN+ReLU transform ---
#pragma unroll
        for (int it = tid; it < 512; it += 256) {
            int r  = it >> 3;
            int kq = it & 7;
            float4 v = *(const float4*)(A + (size_t)(row0 + r) * CH + k0 + kq * 4);
            if (fuse) {
                float4 s = *(const float4*)(st_in + k0 + kq * 4);
                float4 t = *(const float4*)(st_in + CH + k0 + kq * 4);
                v.x = fmaxf(fmaf(v.x, s.x, t.x), 0.f);
                v.y = fmaxf(fmaf(v.y, s.y, t.y), 0.f);
                v.z = fmaxf(fmaf(v.z, s.z, t.z), 0.f);
                v.w = fmaxf(fmaf(v.w, s.w, t.w), 0.f);
            }
            *(float4*)&sA[r][kq * 4] = v;
        }
        // --- load B tile (32x192) ---
#pragma unroll
        for (int it = tid; it < 1536; it += 256) {
            int kk = it / 48;
            int cq = it - kk * 48;
            *(float4*)&sB[kk][cq * 4] =
                *(const float4*)(W + (size_t)(k0 + kk) * CH + cq * 4);
        }
        __syncthreads();

#pragma unroll
        for (int kk4 = 0; kk4 < 8; kk4++) {
            float4 av[8];
#pragma unroll
            for (int r = 0; r < 8; r++)
                av[r] = *(const float4*)&sA[ty * 8 + r][kk4 * 4];
#pragma unroll
            for (int j = 0; j < 4; j++) {
                float bv[6];
#pragma unroll
                for (int q = 0; q < 6; q++)
                    bv[q] = sB[kk4 * 4 + j][tx + 32 * q];
#pragma unroll
                for (int r = 0; r < 8; r++) {
                    float a = (j == 0) ? av[r].x : (j == 1) ? av[r].y
                            : (j == 2) ? av[r].z : av[r].w;
#pragma unroll
                    for (int q = 0; q < 6; q++)
                        acc[r][q] = fmaf(a, bv[q], acc[r][q]);
                }
            }
        }
        __syncthreads();
    }

    // --- write out + per-channel stats ---
    float cs[6], c2[6];
#pragma unroll
    for (int q = 0; q < 6; q++) { cs[q] = 0.f; c2[q] = 0.f; }
#pragma unroll
    for (int r = 0; r < 8; r++) {
        float* orow = out + (size_t)(row0 + ty * 8 + r) * CH;
#pragma unroll
        for (int q = 0; q < 6; q++) {
            float v = acc[r][q];
            orow[tx + 32 * q] = v;
            cs[q] += v;
            c2[q] = fmaf(v, v, c2[q]);
        }
    }
#pragma unroll
    for (int q = 0; q < 6; q++) {
        atomicAdd(&gsum[tx + 32 * q], cs[q]);
        atomicAdd(&gsq [tx + 32 * q], c2[q]);
    }
}

// ---------------------------------------------------------------------------
// Depthwise kernel-point conv, 2-D register-blocked, 2 pairs (4 pts) / phase.
// Block = 192 threads; thread (cg,hg) = (tid>>2, tid&3) owns 4 channels x
// 4 neighbors, for BOTH pairs, with the 2 points of each pair packed f32x2.
// Per k: 1 LDS.128 (w, shared by both pairs) + 4 broadcast LDS.128 (infl)
// feed 32 FFMA2. Influence layout [k][pair*32 + 2h + p].
// h-sum finished by 2-step shfl over the 4-lane quad.
__global__ __launch_bounds__(192, 2) void conv_kernel(
    const float* __restrict__ coord, const int* __restrict__ ref_idx,
    const float* __restrict__ kp, const float* __restrict__ tmp1,
    const float* __restrict__ st1, const float* __restrict__ Wk,
    float* __restrict__ out,
    float* __restrict__ gsum, float* __restrict__ gsq)
{
    __shared__ __align__(16) float s_wk[NK * CH];        // 33024 B
    __shared__ __align__(16) float s_infl[NK][64];       // 11008 B
    __shared__ int   s_ref[4][NH];
    __shared__ float s_nb[4][NH][3];
    __shared__ float s_kp[NK * 3];

    const int tid  = threadIdx.x;
    const int cg   = tid >> 2;       // channel group 0..47
    const int hg   = tid & 3;        // h group 0..3
    const int base = blockIdx.x * PTS_PER_BLK;

    for (int i = tid; i < NK * CH; i += 192) s_wk[i] = Wk[i];
    for (int i = tid; i < NK * 3;  i += 192) s_kp[i] = kp[i];

    // BN1 consts for my 4 channels
    const float4 s4 = *(const float4*)(st1 + cg * 4);
    const float4 t4 = *(const float4*)(st1 + CH + cg * 4);

    float ls[4] = {0.f, 0.f, 0.f, 0.f};
    float lq[4] = {0.f, 0.f, 0.f, 0.f};

#pragma unroll 1
    for (int ph = 0; ph < NPHASE; ph++) {
        const int n0 = base + ph * 4;
        __syncthreads();   // previous phase done reading s_infl / s_ref
        // --- neighbor indices + relative coords for the 4 points ---
        if (tid < 64) {
            int pt = tid >> 4;       // 0..3
            int h  = tid & 15;
            int n  = n0 + pt;
            int r  = ref_idx[n * NH + h];
            s_ref[pt][h] = r;
            s_nb[pt][h][0] = coord[r * 3 + 0] - coord[n * 3 + 0];
            s_nb[pt][h][1] = coord[r * 3 + 1] - coord[n * 3 + 1];
            s_nb[pt][h][2] = coord[r * 3 + 2] - coord[n * 3 + 2];
        }
        __syncthreads();
        // --- influence [k][pair*32 + 2h + p] for 4 points ---
        for (int i = tid; i < NK * 64; i += 192) {
            int k    = i >> 6;
            int rem  = i & 63;
            int pair = rem >> 5;
            int q    = rem & 31;
            int h    = q >> 1;
            int p    = q & 1;
            int pt   = pair * 2 + p;
            float dx = s_nb[pt][h][0] - s_kp[k * 3 + 0];
            float dy = s_nb[pt][h][1] - s_kp[k * 3 + 1];
            float dz = s_nb[pt][h][2] - s_kp[k * 3 + 2];
            float d  = fast_sqrt(fmaf(dx, dx, fmaf(dy, dy, dz * dz)));
            s_infl[k][rem] = fmaxf(1.0f - d, 0.0f);   // SIGMA == 1
        }
        __syncthreads();

        // --- k-loop: acc[pair][j_h][j_c] (f32x2 over the pair's 2 points) ---
        ull acc[2][4][4];
#pragma unroll
        for (int pr = 0; pr < 2; pr++)
#pragma unroll
            for (int j = 0; j < 4; j++)
#pragma unroll
                for (int c = 0; c < 4; c++) acc[pr][j][c] = 0ull;

#pragma unroll 8
        for (int k = 0; k < NK; k++) {
            const float4 wv = *(const float4*)&s_wk[k * CH + cg * 4];
            ull w0 = pack2(wv.x, wv.x);
            ull w1 = pack2(wv.y, wv.y);
            ull w2 = pack2(wv.z, wv.z);
            ull w3 = pack2(wv.w, wv.w);
            const ulonglong2 ua = *(const ulonglong2*)&s_infl[k][hg * 8];
            const ulonglong2 ub = *(const ulonglong2*)&s_infl[k][hg * 8 + 4];
            const ulonglong2 uc = *(const ulonglong2*)&s_infl[k][32 + hg * 8];
            const ulonglong2 ud = *(const ulonglong2*)&s_infl[k][32 + hg * 8 + 4];
            ffma2(acc[0][0][0], ua.x, w0); ffma2(acc[0][0][1], ua.x, w1);
            ffma2(acc[0][0][2], ua.x, w2); ffma2(acc[0][0][3], ua.x, w3);
            ffma2(acc[0][1][0], ua.y, w0); ffma2(acc[0][1][1], ua.y, w1);
            ffma2(acc[0][1][2], ua.y, w2); ffma2(acc[0][1][3], ua.y, w3);
            ffma2(acc[0][2][0], ub.x, w0); ffma2(acc[0][2][1], ub.x, w1);
            ffma2(acc[0][2][2], ub.x, w2); ffma2(acc[0][2][3], ub.x, w3);
            ffma2(acc[0][3][0], ub.y, w0); ffma2(acc[0][3][1], ub.y, w1);
            ffma2(acc[0][3][2], ub.y, w2); ffma2(acc[0][3][3], ub.y, w3);
            ffma2(acc[1][0][0], uc.x, w0); ffma2(acc[1][0][1], uc.x, w1);
            ffma2(acc[1][0][2], uc.x, w2); ffma2(acc[1][0][3], uc.x, w3);
            ffma2(acc[1][1][0], uc.y, w0); ffma2(acc[1][1][1], uc.y, w1);
            ffma2(acc[1][1][2], uc.y, w2); ffma2(acc[1][1][3], uc.y, w3);
            ffma2(acc[1][2][0], ud.x, w0); ffma2(acc[1][2][1], ud.x, w1);
            ffma2(acc[1][2][2], ud.x, w2); ffma2(acc[1][2][3], ud.x, w3);
            ffma2(acc[1][3][0], ud.y, w0); ffma2(acc[1][3][1], ud.y, w1);
            ffma2(acc[1][3][2], ud.y, w2); ffma2(acc[1][3][3], ud.y, w3);
        }

        // --- gather + aggregate, per pair ---
#pragma unroll
        for (int pr = 0; pr < 2; pr++) {
            const int pta = pr * 2, ptb = pr * 2 + 1;
            float po0[4] = {0.f, 0.f, 0.f, 0.f};
            float po1[4] = {0.f, 0.f, 0.f, 0.f};
#pragma unroll
            for (int j = 0; j < 4; j++) {
                int h = hg * 4 + j;
                float4 x0 = *(const float4*)(tmp1 + (size_t)s_ref[pta][h] * CH + cg * 4);
                float4 x1 = *(const float4*)(tmp1 + (size_t)s_ref[ptb][h] * CH + cg * 4);
                x0.x = fmaxf(fmaf(x0.x, s4.x, t4.x), 0.f);
                x0.y = fmaxf(fmaf(x0.y, s4.y, t4.y), 0.f);
                x0.z = fmaxf(fmaf(x0.z, s4.z, t4.z), 0.f);
                x0.w = fmaxf(fmaf(x0.w, s4.w, t4.w), 0.f);
                x1.x = fmaxf(fmaf(x1.x, s4.x, t4.x), 0.f);
                x1.y = fmaxf(fmaf(x1.y, s4.y, t4.y), 0.f);
                x1.z = fmaxf(fmaf(x1.z, s4.z, t4.z), 0.f);
                x1.w = fmaxf(fmaf(x1.w, s4.w, t4.w), 0.f);
                float2 a0 = unpack2(acc[pr][j][0]);
                float2 a1 = unpack2(acc[pr][j][1]);
                float2 a2 = unpack2(acc[pr][j][2]);
                float2 a3 = unpack2(acc[pr][j][3]);
                po0[0] = fmaf(a0.x, x0.x, po0[0]); po1[0] = fmaf(a0.y, x1.x, po1[0]);
                po0[1] = fmaf(a1.x, x0.y, po0[1]); po1[1] = fmaf(a1.y, x1.y, po1[1]);
                po0[2] = fmaf(a2.x, x0.z, po0[2]); po1[2] = fmaf(a2.y, x1.z, po1[2]);
                po0[3] = fmaf(a3.x, x0.w, po0[3]); po1[3] = fmaf(a3.y, x1.w, po1[3]);
            }

            // quad reduction over hg (lanes tid&3)
#pragma unroll
            for (int c = 0; c < 4; c++) {
                po0[c] += __shfl_xor_sync(0xffffffffu, po0[c], 1);
                po0[c] += __shfl_xor_sync(0xffffffffu, po0[c], 2);
                po1[c] += __shfl_xor_sync(0xffffffffu, po1[c], 1);
                po1[c] += __shfl_xor_sync(0xffffffffu, po1[c], 2);
            }

            if (hg == 0) {
                float4 o0 = make_float4(po0[0], po0[1], po0[2], po0[3]);
                float4 o1 = make_float4(po1[0], po1[1], po1[2], po1[3]);
                *(float4*)(out + (size_t)(n0 + pta) * CH + cg * 4) = o0;
                *(float4*)(out + (size_t)(n0 + ptb) * CH + cg * 4) = o1;
#pragma unroll
                for (int c = 0; c < 4; c++) {
                    ls[c] += po0[c] + po1[c];
                    lq[c] = fmaf(po0[c], po0[c], fmaf(po1[c], po1[c], lq[c]));
                }
            }
        }
    }
    if (hg == 0) {
#pragma unroll
        for (int c = 0; c < 4; c++) {
            atomicAdd(&gsum[cg * 4 + c], ls[c]);
            atomicAdd(&gsq [cg * 4 + c], lq[c]);
        }
    }
}

// ---------------------------------------------------------------------------
// feat_out = relu(identity + BN3(tmp3))   (vectorized float4)
__global__ __launch_bounds__(256) void apply3_kernel(
    const float4* __restrict__ idf, const float4* __restrict__ t3,
    const float* __restrict__ st, float4* __restrict__ outf)
{
    int i  = blockIdx.x * blockDim.x + threadIdx.x;   // < NPTS*CH/4
    int cq = i % (CH / 4);
    float4 s = *(const float4*)(st + cq * 4);
    float4 t = *(const float4*)(st + CH + cq * 4);
    float4 x = t3[i];
    float4 d = idf[i];
    float4 r;
    r.x = fmaxf(d.x + fmaf(x.x, s.x, t.x), 0.f);
    r.y = fmaxf(d.y + fmaf(x.y, s.y, t.y), 0.f);
    r.z = fmaxf(d.z + fmaf(x.z, s.z, t.z), 0.f);
    r.w = fmaxf(d.w + fmaf(x.w, s.w, t.w), 0.f);
    outf[i] = r;
}

// ---------------------------------------------------------------------------
extern "C" void kernel_launch(void* const* d_in, const int* in_sizes, int n_in,
                              void* d_out, int out_size)
{
    const float* coord   = (const float*)d_in[0];
    const float* feat    = (const float*)d_in[1];
    const int*   ref_idx = (const int*)  d_in[2];
    const float* kp      = (const float*)d_in[3];
    const float* W1      = (const float*)d_in[4];
    const float* Wk      = (const float*)d_in[5];
    const float* W3      = (const float*)d_in[6];
    const float* g1      = (const float*)d_in[7];
    const float* b1      = (const float*)d_in[8];
    const float* g2      = (const float*)d_in[9];
    const float* b2      = (const float*)d_in[10];
    const float* g3      = (const float*)d_in[11];
    const float* b3      = (const float*)d_in[12];
    float* out = (float*)d_out;

    float *tmp1, *tmp2, *tmp3, *featbuf, *stats, *st;
    cudaGetSymbolAddress((void**)&tmp1,    g_tmp1);
    cudaGetSymbolAddress((void**)&tmp2,    g_tmp2);
    cudaGetSymbolAddress((void**)&tmp3,    g_tmp3);
    cudaGetSymbolAddress((void**)&featbuf, g_featbuf);
    cudaGetSymbolAddress((void**)&stats,   g_stats);
    cudaGetSymbolAddress((void**)&st,      g_st);

    zero_stats_kernel<<<1, 256>>>(stats);

    const int NVEC = NPTS * CH / 4;             // 786432
    for (int i = 0; i < DEPTH; i++) {
        const float* fin_ = (i == 0) ? feat : featbuf;
        float* fout = (i == DEPTH - 1) ? out : featbuf;
        const int s0 = 3 * i + 0, s1 = 3 * i + 1, s2 = 3 * i + 2;

        // fc1 (+BN1 stats)
        gemm192_kernel<<<NPTS / 64, 256>>>(
            fin_, W1 + (size_t)i * CH * CH, tmp1, nullptr, 0,
            stats + s0 * 2 * CH, stats + s0 * 2 * CH + CH);
        fin_kernel<<<1, CH>>>(stats + s0 * 2 * CH, g1 + i * CH, b1 + i * CH,
                              st + s0 * 2 * CH);

        // KP depthwise conv (BN1+ReLU fused at gather; BN2 stats out)
        conv_kernel<<<NPTS / PTS_PER_BLK, CH>>>(
            coord, ref_idx, kp, tmp1, st + s0 * 2 * CH,
            Wk + (size_t)i * NK * CH, tmp2,
            stats + s1 * 2 * CH, stats + s1 * 2 * CH + CH);
        fin_kernel<<<1, CH>>>(stats + s1 * 2 * CH, g2 + i * CH, b2 + i * CH,
                              st + s1 * 2 * CH);

        // fc3 (BN2+ReLU fused on A load; BN3 stats out)
        gemm192_kernel<<<NPTS / 64, 256>>>(
            tmp2, W3 + (size_t)i * CH * CH, tmp3, st + s1 * 2 * CH, 1,
            stats + s2 * 2 * CH, stats + s2 * 2 * CH + CH);
        fin_kernel<<<1, CH>>>(stats + s2 * 2 * CH, g3 + i * CH, b3 + i * CH,
                              st + s2 * 2 * CH);

        // skip + BN3 + ReLU
        apply3_kernel<<<NVEC / 256, 256>>>(
            (const float4*)fin_, (const float4*)tmp3, st + s2 * 2 * CH,
            (float4*)fout);
    }
}